// round 15
// baseline (speedup 1.0000x reference)
#include <cuda_runtime.h>
#include <cstdint>

#define B 8
#define TE 512
#define TD 256
#define H 256

typedef unsigned long long ull;

// Scratch (device globals: no allocations allowed)
__device__ float g_WeT[B * H * TE];  // [b][h][i]
__device__ float g_Uh [B * TD * H];  // [b][j][h]

__device__ __forceinline__ float tanh_fast(float x) {
    float y;
    asm("tanh.approx.f32 %0, %1;" : "=f"(y) : "f"(x));
    return y;
}

// ---- packed fp32x2 helpers ----
__device__ __forceinline__ ull pk2(float lo, float hi) {
    ull r; asm("mov.b64 %0, {%1, %2};" : "=l"(r) : "f"(lo), "f"(hi)); return r;
}
__device__ __forceinline__ ull fma2(ull a, ull b, ull c) {
    ull d; asm("fma.rn.f32x2 %0, %1, %2, %3;" : "=l"(d) : "l"(a), "l"(b), "l"(c)); return d;
}
__device__ __forceinline__ void upk2(ull v, float& lo, float& hi) {
    asm("mov.b64 {%0, %1}, %2;" : "=f"(lo), "=f"(hi) : "l"(v));
}

// 8x4 micro step: 4 row-pairs (reinterpreted from two float4 = FREE packs)
// x 4 dup'd cols (4 MOVs) -> 16 FFMA2.
__device__ __forceinline__ void micro8x4(ull acc[4][4], float4 a0, float4 a1, float4 bb) {
    ull pa[4];
    pa[0] = ((const ull*)&a0)[0];   // (a0.x, a0.y) — bit identical to pk2
    pa[1] = ((const ull*)&a0)[1];
    pa[2] = ((const ull*)&a1)[0];
    pa[3] = ((const ull*)&a1)[1];
    ull pb0 = pk2(bb.x, bb.x);
    ull pb1 = pk2(bb.y, bb.y);
    ull pb2 = pk2(bb.z, bb.z);
    ull pb3 = pk2(bb.w, bb.w);
#pragma unroll
    for (int rp = 0; rp < 4; rp++) {
        acc[rp][0] = fma2(pa[rp], pb0, acc[rp][0]);
        acc[rp][1] = fma2(pa[rp], pb1, acc[rp][1]);
        acc[rp][2] = fma2(pa[rp], pb2, acc[rp][2]);
        acc[rp][3] = fma2(pa[rp], pb3, acc[rp][3]);
    }
}

// ---------------------------------------------------------------------------
// Fused GEMM, 128x64 tiles, 8x4 micro, double-buffered. Grid (24,1,B), 256 thr.
// x<16 : WeT tile  rows=h(128) from W,  cols=i(64) from enc^T
// x>=16: Uh  tile  rows=j(128) from dec^T, cols=h(64) from U
// ---------------------------------------------------------------------------
__global__ __launch_bounds__(256) void gemm_fused(const float* __restrict__ enc,
                                                  const float* __restrict__ dec,
                                                  const float* __restrict__ W,
                                                  const float* __restrict__ U) {
    __shared__ float As[2][16][128];   // [buf][k][row]
    __shared__ float Bs[2][16][68];    // [buf][k][col] (padded)

    int b = blockIdx.z;
    int t = threadIdx.x;
    int tx = t & 15;       // col-group (4 cols)
    int ty = t >> 4;       // row-group (8 rows)

    ull acc[4][4];
#pragma unroll
    for (int rp = 0; rp < 4; rp++)
#pragma unroll
        for (int c = 0; c < 4; c++) acc[rp][c] = 0ull;

    bool weT = (blockIdx.x < 16);

    if (weT) {
        int rh0 = (blockIdx.x >> 3) * 128;   // h row-block
        int ci0 = (blockIdx.x & 7) * 64;     // i col-block
        const float* encb = enc + (size_t)b * TE * H;

        int ka = t >> 4, hq = t & 15;        // As loader
        int ii = t >> 2, kq = t & 3;         // Bs loader

        // stage k-tile 0
        {
            float4 w0 = *(const float4*)&W[ka * H + rh0 + hq * 4];
            float4 w1 = *(const float4*)&W[ka * H + rh0 + 64 + hq * 4];
            float4 e0 = *(const float4*)&encb[(ci0 + ii) * H + kq * 4];
            *(float4*)&As[0][ka][hq * 4]      = w0;
            *(float4*)&As[0][ka][64 + hq * 4] = w1;
            Bs[0][kq * 4 + 0][ii] = e0.x;
            Bs[0][kq * 4 + 1][ii] = e0.y;
            Bs[0][kq * 4 + 2][ii] = e0.z;
            Bs[0][kq * 4 + 3][ii] = e0.w;
        }
        __syncthreads();

#pragma unroll 1
        for (int kt = 0; kt < 16; kt++) {
            int cur = kt & 1;
            float4 w0, w1, e0;
            if (kt < 15) {
                int k0 = (kt + 1) * 16;
                w0 = *(const float4*)&W[(k0 + ka) * H + rh0 + hq * 4];
                w1 = *(const float4*)&W[(k0 + ka) * H + rh0 + 64 + hq * 4];
                e0 = *(const float4*)&encb[(ci0 + ii) * H + k0 + kq * 4];
            }
#pragma unroll
            for (int kk = 0; kk < 16; kk++) {
                float4 a0 = *(float4*)&As[cur][kk][ty * 8];
                float4 a1 = *(float4*)&As[cur][kk][ty * 8 + 4];
                float4 bb = *(float4*)&Bs[cur][kk][tx * 4];
                micro8x4(acc, a0, a1, bb);
            }
            if (kt < 15) {
                int nxt = cur ^ 1;
                *(float4*)&As[nxt][ka][hq * 4]      = w0;
                *(float4*)&As[nxt][ka][64 + hq * 4] = w1;
                Bs[nxt][kq * 4 + 0][ii] = e0.x;
                Bs[nxt][kq * 4 + 1][ii] = e0.y;
                Bs[nxt][kq * 4 + 2][ii] = e0.z;
                Bs[nxt][kq * 4 + 3][ii] = e0.w;
                __syncthreads();
            }
        }

        float* out = g_WeT + (size_t)b * H * TE;
#pragma unroll
        for (int rp = 0; rp < 4; rp++) {
            float lo0, hi0, lo1, hi1, lo2, hi2, lo3, hi3;
            upk2(acc[rp][0], lo0, hi0);
            upk2(acc[rp][1], lo1, hi1);
            upk2(acc[rp][2], lo2, hi2);
            upk2(acc[rp][3], lo3, hi3);
            float4 vlo = make_float4(lo0, lo1, lo2, lo3);
            float4 vhi = make_float4(hi0, hi1, hi2, hi3);
            *(float4*)&out[(rh0 + ty * 8 + 2 * rp)     * TE + ci0 + tx * 4] = vlo;
            *(float4*)&out[(rh0 + ty * 8 + 2 * rp + 1) * TE + ci0 + tx * 4] = vhi;
        }
    } else {
        int v = blockIdx.x - 16;
        int rj0 = (v >> 2) * 128;            // j row-block
        int ch0 = (v & 3) * 64;              // h col-block
        const float* decb = dec + (size_t)b * TD * H;

        int jj = t >> 1, kh = (t & 1) * 2;   // As loader (transposed)
        int kb = t >> 4, hq = t & 15;        // Bs loader

        {
            float4 d0 = *(const float4*)&decb[(rj0 + jj) * H + (kh + 0) * 4];
            float4 d1 = *(const float4*)&decb[(rj0 + jj) * H + (kh + 1) * 4];
            float4 u0 = *(const float4*)&U[kb * H + ch0 + hq * 4];
            As[0][(kh + 0) * 4 + 0][jj] = d0.x;
            As[0][(kh + 0) * 4 + 1][jj] = d0.y;
            As[0][(kh + 0) * 4 + 2][jj] = d0.z;
            As[0][(kh + 0) * 4 + 3][jj] = d0.w;
            As[0][(kh + 1) * 4 + 0][jj] = d1.x;
            As[0][(kh + 1) * 4 + 1][jj] = d1.y;
            As[0][(kh + 1) * 4 + 2][jj] = d1.z;
            As[0][(kh + 1) * 4 + 3][jj] = d1.w;
            *(float4*)&Bs[0][kb][hq * 4] = u0;
        }
        __syncthreads();

#pragma unroll 1
        for (int kt = 0; kt < 16; kt++) {
            int cur = kt & 1;
            float4 d0, d1, u0;
            if (kt < 15) {
                int k0 = (kt + 1) * 16;
                d0 = *(const float4*)&decb[(rj0 + jj) * H + k0 + (kh + 0) * 4];
                d1 = *(const float4*)&decb[(rj0 + jj) * H + k0 + (kh + 1) * 4];
                u0 = *(const float4*)&U[(k0 + kb) * H + ch0 + hq * 4];
            }
#pragma unroll
            for (int kk = 0; kk < 16; kk++) {
                float4 a0 = *(float4*)&As[cur][kk][ty * 8];
                float4 a1 = *(float4*)&As[cur][kk][ty * 8 + 4];
                float4 bb = *(float4*)&Bs[cur][kk][tx * 4];
                micro8x4(acc, a0, a1, bb);
            }
            if (kt < 15) {
                int nxt = cur ^ 1;
                As[nxt][(kh + 0) * 4 + 0][jj] = d0.x;
                As[nxt][(kh + 0) * 4 + 1][jj] = d0.y;
                As[nxt][(kh + 0) * 4 + 2][jj] = d0.z;
                As[nxt][(kh + 0) * 4 + 3][jj] = d0.w;
                As[nxt][(kh + 1) * 4 + 0][jj] = d1.x;
                As[nxt][(kh + 1) * 4 + 1][jj] = d1.y;
                As[nxt][(kh + 1) * 4 + 2][jj] = d1.z;
                As[nxt][(kh + 1) * 4 + 3][jj] = d1.w;
                *(float4*)&Bs[nxt][kb][hq * 4] = u0;
                __syncthreads();
            }
        }

        float* out = g_Uh + (size_t)b * TD * H;
#pragma unroll
        for (int rp = 0; rp < 4; rp++) {
            float lo0, hi0, lo1, hi1, lo2, hi2, lo3, hi3;
            upk2(acc[rp][0], lo0, hi0);
            upk2(acc[rp][1], lo1, hi1);
            upk2(acc[rp][2], lo2, hi2);
            upk2(acc[rp][3], lo3, hi3);
            float4 vlo = make_float4(lo0, lo1, lo2, lo3);
            float4 vhi = make_float4(hi0, hi1, hi2, hi3);
            *(float4*)&out[(rj0 + ty * 8 + 2 * rp)     * H + ch0 + tx * 4] = vlo;
            *(float4*)&out[(rj0 + ty * 8 + 2 * rp + 1) * H + ch0 + tx * 4] = vhi;
        }
    }
}

// ---------------------------------------------------------------------------
// Energy + softmax — VERBATIM from R5 (121.3 µs passing version).
// JT=4: 512 blocks, 512 threads, f32 MUFU tanh.
// ---------------------------------------------------------------------------
__global__ __launch_bounds__(512) void energy_kernel(const float* __restrict__ Va,
                                                     float* __restrict__ e_out) {
    __shared__ float Us4[H * 4];     // [h][jj]
    __shared__ float Vs[H];
    __shared__ float red[16][4];
    __shared__ float binv[4];

    int t  = threadIdx.x;
    int b  = blockIdx.x >> 6;            // TD/4 = 64 tiles per batch
    int j0 = (blockIdx.x & 63) * 4;

    for (int idx = t; idx < 4 * H; idx += 512) {
        int jj = idx >> 8;
        int h  = idx & (H - 1);
        Us4[h * 4 + jj] = g_Uh[((size_t)b * TD + j0 + jj) * H + h];
    }
    if (t < H) Vs[t] = Va[t];
    __syncthreads();

    const int i = t;
    const float* wp = g_WeT + (size_t)b * H * TE + i;

    float acc0 = 0.f, acc1 = 0.f, acc2 = 0.f, acc3 = 0.f;
#pragma unroll 4
    for (int h = 0; h < H; h++) {
        float w = wp[h * TE];
        float4 u = *(const float4*)&Us4[h * 4];
        float v = Vs[h];
        acc0 = fmaf(v, tanh_fast(w + u.x), acc0);
        acc1 = fmaf(v, tanh_fast(w + u.y), acc1);
        acc2 = fmaf(v, tanh_fast(w + u.z), acc2);
        acc3 = fmaf(v, tanh_fast(w + u.w), acc3);
    }

    float p0 = __expf(acc0);
    float p1 = __expf(acc1);
    float p2 = __expf(acc2);
    float p3 = __expf(acc3);

    int lane = t & 31, wrp = t >> 5;
    float s0 = p0, s1 = p1, s2 = p2, s3 = p3;
#pragma unroll
    for (int o = 16; o; o >>= 1) {
        s0 += __shfl_xor_sync(0xffffffffu, s0, o);
        s1 += __shfl_xor_sync(0xffffffffu, s1, o);
        s2 += __shfl_xor_sync(0xffffffffu, s2, o);
        s3 += __shfl_xor_sync(0xffffffffu, s3, o);
    }
    if (lane == 0) { red[wrp][0] = s0; red[wrp][1] = s1; red[wrp][2] = s2; red[wrp][3] = s3; }
    __syncthreads();
    if (t < 4) {
        float s = 0.f;
#pragma unroll
        for (int w2 = 0; w2 < 16; w2++) s += red[w2][t];
        binv[t] = 1.0f / s;
    }
    __syncthreads();

    float* e0 = e_out + ((size_t)b * TD + j0) * TE;
    e0[0 * TE + i] = p0 * binv[0];
    e0[1 * TE + i] = p1 * binv[1];
    e0[2 * TE + i] = p2 * binv[2];
    e0[3 * TE + i] = p3 * binv[3];
}

// ---------------------------------------------------------------------------
// Context GEMM, 128x64 tiles, 8x4 micro, double-buffered. Grid (8,1,B), 256 thr.
// c[b][j][h] = sum_i P[b][j][i] * enc[b][i][h]; K = TE = 512 (32 k-tiles).
// ---------------------------------------------------------------------------
__global__ __launch_bounds__(256) void ctx_gemm(const float* __restrict__ P,
                                                const float* __restrict__ enc,
                                                float* __restrict__ c_out) {
    __shared__ float As[2][16][128];   // [buf][k][j] (P transposed)
    __shared__ float Bs[2][16][68];    // [buf][k][h]

    int b  = blockIdx.z;
    int v  = blockIdx.x;
    int j0 = (v >> 2) * 128;
    int h0 = (v & 3) * 64;
    int t  = threadIdx.x;
    int tx = t & 15;
    int ty = t >> 4;

    ull acc[4][4];
#pragma unroll
    for (int rp = 0; rp < 4; rp++)
#pragma unroll
        for (int c = 0; c < 4; c++) acc[rp][c] = 0ull;

    const float* Pb = P   + (size_t)b * TD * TE;
    const float* eb = enc + (size_t)b * TE * H;

    int jj = t >> 1, kh = (t & 1) * 2;   // As loader (transposed)
    int kb = t >> 4, hq = t & 15;        // Bs loader

    {
        float4 p0 = *(const float4*)&Pb[(j0 + jj) * TE + (kh + 0) * 4];
        float4 p1 = *(const float4*)&Pb[(j0 + jj) * TE + (kh + 1) * 4];
        float4 e0 = *(const float4*)&eb[kb * H + h0 + hq * 4];
        As[0][(kh + 0) * 4 + 0][jj] = p0.x;
        As[0][(kh + 0) * 4 + 1][jj] = p0.y;
        As[0][(kh + 0) * 4 + 2][jj] = p0.z;
        As[0][(kh + 0) * 4 + 3][jj] = p0.w;
        As[0][(kh + 1) * 4 + 0][jj] = p1.x;
        As[0][(kh + 1) * 4 + 1][jj] = p1.y;
        As[0][(kh + 1) * 4 + 2][jj] = p1.z;
        As[0][(kh + 1) * 4 + 3][jj] = p1.w;
        *(float4*)&Bs[0][kb][hq * 4] = e0;
    }
    __syncthreads();

#pragma unroll 1
    for (int kt = 0; kt < 32; kt++) {
        int cur = kt & 1;
        float4 p0, p1, e0;
        if (kt < 31) {
            int k0 = (kt + 1) * 16;
            p0 = *(const float4*)&Pb[(j0 + jj) * TE + k0 + (kh + 0) * 4];
            p1 = *(const float4*)&Pb[(j0 + jj) * TE + k0 + (kh + 1) * 4];
            e0 = *(const float4*)&eb[(k0 + kb) * H + h0 + hq * 4];
        }
#pragma unroll
        for (int kk = 0; kk < 16; kk++) {
            float4 a0 = *(float4*)&As[cur][kk][ty * 8];
            float4 a1 = *(float4*)&As[cur][kk][ty * 8 + 4];
            float4 bb = *(float4*)&Bs[cur][kk][tx * 4];
            micro8x4(acc, a0, a1, bb);
        }
        if (kt < 31) {
            int nxt = cur ^ 1;
            As[nxt][(kh + 0) * 4 + 0][jj] = p0.x;
            As[nxt][(kh + 0) * 4 + 1][jj] = p0.y;
            As[nxt][(kh + 0) * 4 + 2][jj] = p0.z;
            As[nxt][(kh + 0) * 4 + 3][jj] = p0.w;
            As[nxt][(kh + 1) * 4 + 0][jj] = p1.x;
            As[nxt][(kh + 1) * 4 + 1][jj] = p1.y;
            As[nxt][(kh + 1) * 4 + 2][jj] = p1.z;
            As[nxt][(kh + 1) * 4 + 3][jj] = p1.w;
            *(float4*)&Bs[nxt][kb][hq * 4] = e0;
            __syncthreads();
        }
    }

#pragma unroll
    for (int rp = 0; rp < 4; rp++) {
        float lo0, hi0, lo1, hi1, lo2, hi2, lo3, hi3;
        upk2(acc[rp][0], lo0, hi0);
        upk2(acc[rp][1], lo1, hi1);
        upk2(acc[rp][2], lo2, hi2);
        upk2(acc[rp][3], lo3, hi3);
        float4 vlo = make_float4(lo0, lo1, lo2, lo3);
        float4 vhi = make_float4(hi0, hi1, hi2, hi3);
        *(float4*)&c_out[((size_t)b * TD + j0 + ty * 8 + 2 * rp)     * H + h0 + tx * 4] = vlo;
        *(float4*)&c_out[((size_t)b * TD + j0 + ty * 8 + 2 * rp + 1) * H + h0 + tx * 4] = vhi;
    }
}

// ---------------------------------------------------------------------------
extern "C" void kernel_launch(void* const* d_in, const int* in_sizes, int n_in,
                              void* d_out, int out_size) {
    const float* enc = (const float*)d_in[0];  // [B,TE,H]
    const float* dec = (const float*)d_in[1];  // [B,TD,H]
    const float* W   = (const float*)d_in[2];  // [H,H]
    const float* U   = (const float*)d_in[3];  // [H,H]
    const float* V   = (const float*)d_in[4];  // [H,1]

    float* c_out = (float*)d_out;              // [B,TD,H]
    float* e_out = (float*)d_out + B * TD * H; // [B,TD,TE]

    dim3 gg(24, 1, B);
    gemm_fused<<<gg, 256>>>(enc, dec, W, U);
    energy_kernel<<<B * (TD / 4), 512>>>(V, e_out);
    dim3 gc(8, 1, B);
    ctx_gemm<<<gc, 256>>>(e_out, enc, c_out);
}

// round 16
// speedup vs baseline: 1.4390x; 1.4390x over previous
#include <cuda_runtime.h>
#include <cstdint>

#define B 8
#define TE 512
#define TD 256
#define H 256

typedef unsigned long long ull;

// Scratch (device globals: no allocations allowed)
__device__ float g_WeT[B * H * TE];  // [b][h][i]
__device__ float g_Uh [B * TD * H];  // [b][j][h]

__device__ __forceinline__ float tanh_fast(float x) {
    float y;
    asm("tanh.approx.f32 %0, %1;" : "=f"(y) : "f"(x));
    return y;
}

// ---- packed fp32x2 helpers ----
__device__ __forceinline__ ull pk2(float lo, float hi) {
    ull r; asm("mov.b64 %0, {%1, %2};" : "=l"(r) : "f"(lo), "f"(hi)); return r;
}
__device__ __forceinline__ ull fma2(ull a, ull b, ull c) {
    ull d; asm("fma.rn.f32x2 %0, %1, %2, %3;" : "=l"(d) : "l"(a), "l"(b), "l"(c)); return d;
}
__device__ __forceinline__ void upk2(ull v, float& lo, float& hi) {
    asm("mov.b64 {%0, %1}, %2;" : "=f"(lo), "=f"(hi) : "l"(v));
}

// 2x4 micro step: one row-pair (from LDS.64) x 4 dup'd cols -> 4 FFMA2
__device__ __forceinline__ void micro2x4(ull acc[4], float2 a, float4 bb) {
    ull pa = pk2(a.x, a.y);
    acc[0] = fma2(pa, pk2(bb.x, bb.x), acc[0]);
    acc[1] = fma2(pa, pk2(bb.y, bb.y), acc[1]);
    acc[2] = fma2(pa, pk2(bb.z, bb.z), acc[2]);
    acc[3] = fma2(pa, pk2(bb.w, bb.w), acc[3]);
}

// ---------------------------------------------------------------------------
// Fused GEMM, 32(rows)x64(cols) tiles, 2x4 micro, double-buffered.
// Grid (96,1,B), 256 threads -> 768 blocks total.
//   x<64 : WeT tile  rows=h(32) from W,     cols=i(64) from enc^T
//   x>=64: Uh  tile  rows=j(32) from dec^T, cols=h(64) from U
// As = rows buffer [2][16][32], Bs = cols buffer [2][16][68] (padded).
// ---------------------------------------------------------------------------
__global__ __launch_bounds__(256) void gemm_fused(const float* __restrict__ enc,
                                                  const float* __restrict__ dec,
                                                  const float* __restrict__ W,
                                                  const float* __restrict__ U) {
    __shared__ float As[2][16][32];
    __shared__ float Bs[2][16][68];

    int b = blockIdx.z;
    int t = threadIdx.x;
    int tx = t & 15;       // col quad (4 cols)
    int ty = t >> 4;       // row pair (2 rows)

    ull acc[4];
#pragma unroll
    for (int c = 0; c < 4; c++) acc[c] = 0ull;

    bool weT = (blockIdx.x < 64);

    if (weT) {
        int rh0 = (blockIdx.x >> 3) * 32;    // h row-block
        int ci0 = (blockIdx.x & 7) * 64;     // i col-block
        const float* encb = enc + (size_t)b * TE * H;

        int ka = t >> 3, hq = t & 7;         // As loader (t<128)
        int ii = t >> 2, kq = t & 3;         // Bs loader (all)

        {
            if (t < 128) {
                float4 w0 = *(const float4*)&W[ka * H + rh0 + hq * 4];
                *(float4*)&As[0][ka][hq * 4] = w0;
            }
            float4 e0 = *(const float4*)&encb[(ci0 + ii) * H + kq * 4];
            Bs[0][kq * 4 + 0][ii] = e0.x;
            Bs[0][kq * 4 + 1][ii] = e0.y;
            Bs[0][kq * 4 + 2][ii] = e0.z;
            Bs[0][kq * 4 + 3][ii] = e0.w;
        }
        __syncthreads();

#pragma unroll 1
        for (int kt = 0; kt < 16; kt++) {
            int cur = kt & 1;
            float4 w0, e0;
            if (kt < 15) {
                int k0 = (kt + 1) * 16;
                if (t < 128)
                    w0 = *(const float4*)&W[(k0 + ka) * H + rh0 + hq * 4];
                e0 = *(const float4*)&encb[(ci0 + ii) * H + k0 + kq * 4];
            }
#pragma unroll
            for (int kk = 0; kk < 16; kk++) {
                float2 a  = *(float2*)&As[cur][kk][ty * 2];
                float4 bb = *(float4*)&Bs[cur][kk][tx * 4];
                micro2x4(acc, a, bb);
            }
            if (kt < 15) {
                int nxt = cur ^ 1;
                if (t < 128)
                    *(float4*)&As[nxt][ka][hq * 4] = w0;
                Bs[nxt][kq * 4 + 0][ii] = e0.x;
                Bs[nxt][kq * 4 + 1][ii] = e0.y;
                Bs[nxt][kq * 4 + 2][ii] = e0.z;
                Bs[nxt][kq * 4 + 3][ii] = e0.w;
                __syncthreads();
            }
        }

        float o[2][4];
#pragma unroll
        for (int c = 0; c < 4; c++) upk2(acc[c], o[0][c], o[1][c]);
        float* out = g_WeT + (size_t)b * H * TE;
#pragma unroll
        for (int r = 0; r < 2; r++) {
            float4 v = make_float4(o[r][0], o[r][1], o[r][2], o[r][3]);
            *(float4*)&out[(rh0 + ty * 2 + r) * TE + ci0 + tx * 4] = v;
        }
    } else {
        int v   = blockIdx.x - 64;
        int rj0 = (v >> 2) * 32;             // j row-block
        int ch0 = (v & 3) * 64;              // h col-block
        const float* decb = dec + (size_t)b * TD * H;

        int jj = t >> 2, kq = t & 3;         // As loader (transposed, t<128)
        int ka = t >> 4, hq = t & 15;        // Bs loader (all)

        {
            if (t < 128) {
                float4 d0 = *(const float4*)&decb[(rj0 + jj) * H + kq * 4];
                As[0][kq * 4 + 0][jj] = d0.x;
                As[0][kq * 4 + 1][jj] = d0.y;
                As[0][kq * 4 + 2][jj] = d0.z;
                As[0][kq * 4 + 3][jj] = d0.w;
            }
            float4 u0 = *(const float4*)&U[ka * H + ch0 + hq * 4];
            *(float4*)&Bs[0][ka][hq * 4] = u0;
        }
        __syncthreads();

#pragma unroll 1
        for (int kt = 0; kt < 16; kt++) {
            int cur = kt & 1;
            float4 d0, u0;
            if (kt < 15) {
                int k0 = (kt + 1) * 16;
                if (t < 128)
                    d0 = *(const float4*)&decb[(rj0 + jj) * H + k0 + kq * 4];
                u0 = *(const float4*)&U[(k0 + ka) * H + ch0 + hq * 4];
            }
#pragma unroll
            for (int kk = 0; kk < 16; kk++) {
                float2 a  = *(float2*)&As[cur][kk][ty * 2];
                float4 bb = *(float4*)&Bs[cur][kk][tx * 4];
                micro2x4(acc, a, bb);
            }
            if (kt < 15) {
                int nxt = cur ^ 1;
                if (t < 128) {
                    As[nxt][kq * 4 + 0][jj] = d0.x;
                    As[nxt][kq * 4 + 1][jj] = d0.y;
                    As[nxt][kq * 4 + 2][jj] = d0.z;
                    As[nxt][kq * 4 + 3][jj] = d0.w;
                }
                *(float4*)&Bs[nxt][ka][hq * 4] = u0;
                __syncthreads();
            }
        }

        float o[2][4];
#pragma unroll
        for (int c = 0; c < 4; c++) upk2(acc[c], o[0][c], o[1][c]);
        float* out = g_Uh + (size_t)b * TD * H;
#pragma unroll
        for (int r = 0; r < 2; r++) {
            float4 vv = make_float4(o[r][0], o[r][1], o[r][2], o[r][3]);
            *(float4*)&out[(rj0 + ty * 2 + r) * H + ch0 + tx * 4] = vv;
        }
    }
}

// ---------------------------------------------------------------------------
// Energy + softmax — VERBATIM from R5 (121.3 µs passing version).
// JT=4: 512 blocks, 512 threads, f32 MUFU tanh.
// ---------------------------------------------------------------------------
__global__ __launch_bounds__(512) void energy_kernel(const float* __restrict__ Va,
                                                     float* __restrict__ e_out) {
    __shared__ float Us4[H * 4];     // [h][jj]
    __shared__ float Vs[H];
    __shared__ float red[16][4];
    __shared__ float binv[4];

    int t  = threadIdx.x;
    int b  = blockIdx.x >> 6;            // TD/4 = 64 tiles per batch
    int j0 = (blockIdx.x & 63) * 4;

    for (int idx = t; idx < 4 * H; idx += 512) {
        int jj = idx >> 8;
        int h  = idx & (H - 1);
        Us4[h * 4 + jj] = g_Uh[((size_t)b * TD + j0 + jj) * H + h];
    }
    if (t < H) Vs[t] = Va[t];
    __syncthreads();

    const int i = t;
    const float* wp = g_WeT + (size_t)b * H * TE + i;

    float acc0 = 0.f, acc1 = 0.f, acc2 = 0.f, acc3 = 0.f;
#pragma unroll 4
    for (int h = 0; h < H; h++) {
        float w = wp[h * TE];
        float4 u = *(const float4*)&Us4[h * 4];
        float v = Vs[h];
        acc0 = fmaf(v, tanh_fast(w + u.x), acc0);
        acc1 = fmaf(v, tanh_fast(w + u.y), acc1);
        acc2 = fmaf(v, tanh_fast(w + u.z), acc2);
        acc3 = fmaf(v, tanh_fast(w + u.w), acc3);
    }

    float p0 = __expf(acc0);
    float p1 = __expf(acc1);
    float p2 = __expf(acc2);
    float p3 = __expf(acc3);

    int lane = t & 31, wrp = t >> 5;
    float s0 = p0, s1 = p1, s2 = p2, s3 = p3;
#pragma unroll
    for (int o = 16; o; o >>= 1) {
        s0 += __shfl_xor_sync(0xffffffffu, s0, o);
        s1 += __shfl_xor_sync(0xffffffffu, s1, o);
        s2 += __shfl_xor_sync(0xffffffffu, s2, o);
        s3 += __shfl_xor_sync(0xffffffffu, s3, o);
    }
    if (lane == 0) { red[wrp][0] = s0; red[wrp][1] = s1; red[wrp][2] = s2; red[wrp][3] = s3; }
    __syncthreads();
    if (t < 4) {
        float s = 0.f;
#pragma unroll
        for (int w2 = 0; w2 < 16; w2++) s += red[w2][t];
        binv[t] = 1.0f / s;
    }
    __syncthreads();

    float* e0 = e_out + ((size_t)b * TD + j0) * TE;
    e0[0 * TE + i] = p0 * binv[0];
    e0[1 * TE + i] = p1 * binv[1];
    e0[2 * TE + i] = p2 * binv[2];
    e0[3 * TE + i] = p3 * binv[3];
}

// ---------------------------------------------------------------------------
// Context GEMM, 32(j)x64(h) tiles, 2x4 micro, double-buffered.
// Grid (32,1,B), 256 threads -> 256 blocks. K = TE = 512 (32 k-tiles).
// ---------------------------------------------------------------------------
__global__ __launch_bounds__(256) void ctx_gemm(const float* __restrict__ P,
                                                const float* __restrict__ enc,
                                                float* __restrict__ c_out) {
    __shared__ float As[2][16][32];    // [buf][k][j] (P transposed)
    __shared__ float Bs[2][16][68];    // [buf][k][h]

    int b  = blockIdx.z;
    int v  = blockIdx.x;
    int j0 = (v >> 2) * 32;
    int h0 = (v & 3) * 64;
    int t  = threadIdx.x;
    int tx = t & 15;
    int ty = t >> 4;

    ull acc[4];
#pragma unroll
    for (int c = 0; c < 4; c++) acc[c] = 0ull;

    const float* Pb = P   + (size_t)b * TD * TE;
    const float* eb = enc + (size_t)b * TE * H;

    int jj = t >> 2, kq = t & 3;       // As loader (transposed, t<128)
    int ka = t >> 4, hq = t & 15;      // Bs loader (all)

    {
        if (t < 128) {
            float4 p0 = *(const float4*)&Pb[(j0 + jj) * TE + kq * 4];
            As[0][kq * 4 + 0][jj] = p0.x;
            As[0][kq * 4 + 1][jj] = p0.y;
            As[0][kq * 4 + 2][jj] = p0.z;
            As[0][kq * 4 + 3][jj] = p0.w;
        }
        float4 e0 = *(const float4*)&eb[ka * H + h0 + hq * 4];
        *(float4*)&Bs[0][ka][hq * 4] = e0;
    }
    __syncthreads();

#pragma unroll 1
    for (int kt = 0; kt < 32; kt++) {
        int cur = kt & 1;
        float4 p0, e0;
        if (kt < 31) {
            int k0 = (kt + 1) * 16;
            if (t < 128)
                p0 = *(const float4*)&Pb[(j0 + jj) * TE + k0 + kq * 4];
            e0 = *(const float4*)&eb[(k0 + ka) * H + h0 + hq * 4];
        }
#pragma unroll
        for (int kk = 0; kk < 16; kk++) {
            float2 a  = *(float2*)&As[cur][kk][ty * 2];
            float4 bb = *(float4*)&Bs[cur][kk][tx * 4];
            micro2x4(acc, a, bb);
        }
        if (kt < 31) {
            int nxt = cur ^ 1;
            if (t < 128) {
                As[nxt][kq * 4 + 0][jj] = p0.x;
                As[nxt][kq * 4 + 1][jj] = p0.y;
                As[nxt][kq * 4 + 2][jj] = p0.z;
                As[nxt][kq * 4 + 3][jj] = p0.w;
            }
            *(float4*)&Bs[nxt][ka][hq * 4] = e0;
            __syncthreads();
        }
    }

    float o[2][4];
#pragma unroll
    for (int c = 0; c < 4; c++) upk2(acc[c], o[0][c], o[1][c]);
#pragma unroll
    for (int r = 0; r < 2; r++) {
        float4 vv = make_float4(o[r][0], o[r][1], o[r][2], o[r][3]);
        *(float4*)&c_out[((size_t)b * TD + j0 + ty * 2 + r) * H + h0 + tx * 4] = vv;
    }
}

// ---------------------------------------------------------------------------
extern "C" void kernel_launch(void* const* d_in, const int* in_sizes, int n_in,
                              void* d_out, int out_size) {
    const float* enc = (const float*)d_in[0];  // [B,TE,H]
    const float* dec = (const float*)d_in[1];  // [B,TD,H]
    const float* W   = (const float*)d_in[2];  // [H,H]
    const float* U   = (const float*)d_in[3];  // [H,H]
    const float* V   = (const float*)d_in[4];  // [H,1]

    float* c_out = (float*)d_out;              // [B,TD,H]
    float* e_out = (float*)d_out + B * TD * H; // [B,TD,TE]

    dim3 gg(96, 1, B);                         // 64 WeT tiles + 32 Uh tiles
    gemm_fused<<<gg, 256>>>(enc, dec, W, U);
    energy_kernel<<<B * (TD / 4), 512>>>(V, e_out);
    dim3 gc(32, 1, B);
    ctx_gemm<<<gc, 256>>>(e_out, enc, c_out);
}

// round 17
// speedup vs baseline: 1.6971x; 1.1794x over previous
#include <cuda_runtime.h>
#include <cstdint>

#define B 8
#define TE 512
#define TD 256
#define H 256

typedef unsigned long long ull;

// Scratch (device globals: no allocations allowed)
__device__ float g_WeT[B * H * TE];  // [b][h][i]
__device__ float g_Uh [B * TD * H];  // [b][j][h]

__device__ __forceinline__ float tanh_fast(float x) {
    float y;
    asm("tanh.approx.f32 %0, %1;" : "=f"(y) : "f"(x));
    return y;
}

// ---- packed fp32x2 helpers ----
__device__ __forceinline__ ull pk2(float lo, float hi) {
    ull r; asm("mov.b64 %0, {%1, %2};" : "=l"(r) : "f"(lo), "f"(hi)); return r;
}
__device__ __forceinline__ ull fma2(ull a, ull b, ull c) {
    ull d; asm("fma.rn.f32x2 %0, %1, %2, %3;" : "=l"(d) : "l"(a), "l"(b), "l"(c)); return d;
}
__device__ __forceinline__ void upk2(ull v, float& lo, float& hi) {
    asm("mov.b64 {%0, %1}, %2;" : "=f"(lo), "=f"(hi) : "l"(v));
}

// 4x4 micro-tile step, rows packed in pairs, cols duplicated
__device__ __forceinline__ void micro_fma2(ull acc2[2][4], float4 a, float4 bb) {
    ull pa0 = pk2(a.x, a.y);
    ull pa1 = pk2(a.z, a.w);
    ull pb0 = pk2(bb.x, bb.x);
    ull pb1 = pk2(bb.y, bb.y);
    ull pb2 = pk2(bb.z, bb.z);
    ull pb3 = pk2(bb.w, bb.w);
    acc2[0][0] = fma2(pa0, pb0, acc2[0][0]);
    acc2[0][1] = fma2(pa0, pb1, acc2[0][1]);
    acc2[0][2] = fma2(pa0, pb2, acc2[0][2]);
    acc2[0][3] = fma2(pa0, pb3, acc2[0][3]);
    acc2[1][0] = fma2(pa1, pb0, acc2[1][0]);
    acc2[1][1] = fma2(pa1, pb1, acc2[1][1]);
    acc2[1][2] = fma2(pa1, pb2, acc2[1][2]);
    acc2[1][3] = fma2(pa1, pb3, acc2[1][3]);
}

// ---------------------------------------------------------------------------
// Zero scratch (every launch/replay; required for atomic K-split accumulate).
// g_WeT: 1M floats, g_Uh: 0.5M floats -> 6 MB total.
// ---------------------------------------------------------------------------
__global__ __launch_bounds__(256) void zero_kernel() {
    size_t idx = (size_t)blockIdx.x * 256 + threadIdx.x;
    float4 z = make_float4(0.f, 0.f, 0.f, 0.f);
    size_t nW = (size_t)B * H * TE / 4;   // 262144 float4
    size_t nU = (size_t)B * TD * H / 4;   // 131072 float4
    for (size_t i = idx; i < nW; i += (size_t)gridDim.x * 256)
        ((float4*)g_WeT)[i] = z;
    for (size_t i = idx; i < nU; i += (size_t)gridDim.x * 256)
        ((float4*)g_Uh)[i] = z;
}

// ---------------------------------------------------------------------------
// Fused GEMM, K-split in 2 halves (atomicAdd accumulate), double-buffered.
// Grid (24,4,B) = 768 blocks, 256 threads. 64x64 tiles, 8 k-tiles per block.
//   x<16 : WeT  (i-tile = x&7, khalf = x>>3)   rows=h from W, cols=i from enc^T
//   x>=16: Uh   (h-tile = (x-16)&3, khalf = (x-16)>>2) rows=j from dec^T, cols=h
// Exactly 2 atomic fp32 adds per output element -> deterministic result.
// ---------------------------------------------------------------------------
__global__ __launch_bounds__(256) void gemm_fused(const float* __restrict__ enc,
                                                  const float* __restrict__ dec,
                                                  const float* __restrict__ W,
                                                  const float* __restrict__ U) {
    __shared__ float As[2][16][64];
    __shared__ float Bs[2][16][68];

    int b = blockIdx.z;
    int t = threadIdx.x;
    int tx = t & 15;
    int ty = t >> 4;

    ull acc2[2][4];
#pragma unroll
    for (int rp = 0; rp < 2; rp++)
#pragma unroll
        for (int c = 0; c < 4; c++) acc2[rp][c] = 0ull;

    bool weT = (blockIdx.x < 16);
    int kbase;
    const float* Wm;
    const float* act;
    int h0 = blockIdx.y * 64;
    int c0;
    if (weT) {
        Wm  = W;
        act = enc + (size_t)b * TE * H;
        c0  = (blockIdx.x & 7) * 64;
        kbase = (blockIdx.x >> 3) * 128;
    } else {
        int v = blockIdx.x - 16;
        Wm  = U;
        act = dec + (size_t)b * TD * H;
        c0  = (v & 3) * 64;
        kbase = (v >> 2) * 128;
    }

    int ka = t >> 4, hq = t & 15;       // As loader coords
    int cc = t >> 2, kq = t & 3;        // Bs loader coords

    {
        float4 aReg = *(const float4*)&Wm[(kbase + ka) * H + h0 + hq * 4];
        float4 bReg = *(const float4*)&act[(c0 + cc) * H + kbase + kq * 4];
        *(float4*)&As[0][ka][hq * 4] = aReg;
        Bs[0][kq * 4 + 0][cc] = bReg.x;
        Bs[0][kq * 4 + 1][cc] = bReg.y;
        Bs[0][kq * 4 + 2][cc] = bReg.z;
        Bs[0][kq * 4 + 3][cc] = bReg.w;
    }
    __syncthreads();

    if (weT) {
#pragma unroll 1
        for (int kt = 0; kt < 8; kt++) {
            int cur = kt & 1;
            float4 aReg, bReg;
            if (kt < 7) {
                int k0 = kbase + (kt + 1) * 16;
                aReg = *(const float4*)&Wm[(k0 + ka) * H + h0 + hq * 4];
                bReg = *(const float4*)&act[(c0 + cc) * H + k0 + kq * 4];
            }
#pragma unroll
            for (int kk = 0; kk < 16; kk++) {
                float4 a  = *(float4*)&As[cur][kk][ty * 4];
                float4 bb = *(float4*)&Bs[cur][kk][tx * 4];
                micro_fma2(acc2, a, bb);
            }
            if (kt < 7) {
                int nxt = cur ^ 1;
                *(float4*)&As[nxt][ka][hq * 4] = aReg;
                Bs[nxt][kq * 4 + 0][cc] = bReg.x;
                Bs[nxt][kq * 4 + 1][cc] = bReg.y;
                Bs[nxt][kq * 4 + 2][cc] = bReg.z;
                Bs[nxt][kq * 4 + 3][cc] = bReg.w;
                __syncthreads();
            }
        }
        float o[4][4];
#pragma unroll
        for (int rp = 0; rp < 2; rp++)
#pragma unroll
            for (int c = 0; c < 4; c++)
                upk2(acc2[rp][c], o[2 * rp][c], o[2 * rp + 1][c]);
        float* out = g_WeT + (size_t)b * H * TE;
#pragma unroll
        for (int r = 0; r < 4; r++)
#pragma unroll
            for (int c = 0; c < 4; c++)
                atomicAdd(&out[(h0 + ty * 4 + r) * TE + c0 + tx * 4 + c], o[r][c]);
    } else {
#pragma unroll 1
        for (int kt = 0; kt < 8; kt++) {
            int cur = kt & 1;
            float4 aReg, bReg;
            if (kt < 7) {
                int k0 = kbase + (kt + 1) * 16;
                aReg = *(const float4*)&Wm[(k0 + ka) * H + h0 + hq * 4];
                bReg = *(const float4*)&act[(c0 + cc) * H + k0 + kq * 4];
            }
#pragma unroll
            for (int kk = 0; kk < 16; kk++) {
                float4 a  = *(float4*)&Bs[cur][kk][ty * 4];
                float4 bb = *(float4*)&As[cur][kk][tx * 4];
                micro_fma2(acc2, a, bb);
            }
            if (kt < 7) {
                int nxt = cur ^ 1;
                *(float4*)&As[nxt][ka][hq * 4] = aReg;
                Bs[nxt][kq * 4 + 0][cc] = bReg.x;
                Bs[nxt][kq * 4 + 1][cc] = bReg.y;
                Bs[nxt][kq * 4 + 2][cc] = bReg.z;
                Bs[nxt][kq * 4 + 3][cc] = bReg.w;
                __syncthreads();
            }
        }
        float o[4][4];
#pragma unroll
        for (int rp = 0; rp < 2; rp++)
#pragma unroll
            for (int c = 0; c < 4; c++)
                upk2(acc2[rp][c], o[2 * rp][c], o[2 * rp + 1][c]);
        float* out = g_Uh + (size_t)b * TD * H;
#pragma unroll
        for (int r = 0; r < 4; r++)
#pragma unroll
            for (int c = 0; c < 4; c++)
                atomicAdd(&out[(c0 + ty * 4 + r) * H + h0 + tx * 4 + c], o[r][c]);
    }
}

// ---------------------------------------------------------------------------
// Energy + softmax — VERBATIM from R5 (121.3 µs passing version).
// JT=4: 512 blocks, 512 threads, f32 MUFU tanh.
// ---------------------------------------------------------------------------
__global__ __launch_bounds__(512) void energy_kernel(const float* __restrict__ Va,
                                                     float* __restrict__ e_out) {
    __shared__ float Us4[H * 4];     // [h][jj]
    __shared__ float Vs[H];
    __shared__ float red[16][4];
    __shared__ float binv[4];

    int t  = threadIdx.x;
    int b  = blockIdx.x >> 6;            // TD/4 = 64 tiles per batch
    int j0 = (blockIdx.x & 63) * 4;

    for (int idx = t; idx < 4 * H; idx += 512) {
        int jj = idx >> 8;
        int h  = idx & (H - 1);
        Us4[h * 4 + jj] = g_Uh[((size_t)b * TD + j0 + jj) * H + h];
    }
    if (t < H) Vs[t] = Va[t];
    __syncthreads();

    const int i = t;
    const float* wp = g_WeT + (size_t)b * H * TE + i;

    float acc0 = 0.f, acc1 = 0.f, acc2 = 0.f, acc3 = 0.f;
#pragma unroll 4
    for (int h = 0; h < H; h++) {
        float w = wp[h * TE];
        float4 u = *(const float4*)&Us4[h * 4];
        float v = Vs[h];
        acc0 = fmaf(v, tanh_fast(w + u.x), acc0);
        acc1 = fmaf(v, tanh_fast(w + u.y), acc1);
        acc2 = fmaf(v, tanh_fast(w + u.z), acc2);
        acc3 = fmaf(v, tanh_fast(w + u.w), acc3);
    }

    float p0 = __expf(acc0);
    float p1 = __expf(acc1);
    float p2 = __expf(acc2);
    float p3 = __expf(acc3);

    int lane = t & 31, wrp = t >> 5;
    float s0 = p0, s1 = p1, s2 = p2, s3 = p3;
#pragma unroll
    for (int o = 16; o; o >>= 1) {
        s0 += __shfl_xor_sync(0xffffffffu, s0, o);
        s1 += __shfl_xor_sync(0xffffffffu, s1, o);
        s2 += __shfl_xor_sync(0xffffffffu, s2, o);
        s3 += __shfl_xor_sync(0xffffffffu, s3, o);
    }
    if (lane == 0) { red[wrp][0] = s0; red[wrp][1] = s1; red[wrp][2] = s2; red[wrp][3] = s3; }
    __syncthreads();
    if (t < 4) {
        float s = 0.f;
#pragma unroll
        for (int w2 = 0; w2 < 16; w2++) s += red[w2][t];
        binv[t] = 1.0f / s;
    }
    __syncthreads();

    float* e0 = e_out + ((size_t)b * TD + j0) * TE;
    e0[0 * TE + i] = p0 * binv[0];
    e0[1 * TE + i] = p1 * binv[1];
    e0[2 * TE + i] = p2 * binv[2];
    e0[3 * TE + i] = p3 * binv[3];
}

// ---------------------------------------------------------------------------
// Context GEMM — VERBATIM from R5 (double-buffered, 64x64, K=512).
// Grid (H/64, TD/64, B) = 128 blocks.
// ---------------------------------------------------------------------------
__global__ __launch_bounds__(256) void ctx_gemm(const float* __restrict__ P,
                                                const float* __restrict__ enc,
                                                float* __restrict__ c_out) {
    __shared__ float As[2][16][68];
    __shared__ float Bs[2][16][64];

    int b  = blockIdx.z;
    int j0 = blockIdx.y * 64;
    int h0 = blockIdx.x * 64;
    int t  = threadIdx.x;
    int tx = t & 15;
    int ty = t >> 4;

    ull acc2[2][4];
#pragma unroll
    for (int rp = 0; rp < 2; rp++)
#pragma unroll
        for (int c = 0; c < 4; c++) acc2[rp][c] = 0ull;

    const float* Pb = P   + (size_t)b * TD * TE;
    const float* eb = enc + (size_t)b * TE * H;

    int jj = t >> 2, kq = t & 3;
    int kb = t >> 4, hq = t & 15;

    {
        float4 aReg = *(const float4*)&Pb[(j0 + jj) * TE + kq * 4];
        float4 bReg = *(const float4*)&eb[kb * H + h0 + hq * 4];
        As[0][kq * 4 + 0][jj] = aReg.x;
        As[0][kq * 4 + 1][jj] = aReg.y;
        As[0][kq * 4 + 2][jj] = aReg.z;
        As[0][kq * 4 + 3][jj] = aReg.w;
        *(float4*)&Bs[0][kb][hq * 4] = bReg;
    }
    __syncthreads();

#pragma unroll 1
    for (int kt = 0; kt < 32; kt++) {
        int cur = kt & 1;
        float4 aReg, bReg;
        if (kt < 31) {
            int k0 = (kt + 1) * 16;
            aReg = *(const float4*)&Pb[(j0 + jj) * TE + k0 + kq * 4];
            bReg = *(const float4*)&eb[(k0 + kb) * H + h0 + hq * 4];
        }
#pragma unroll
        for (int kk = 0; kk < 16; kk++) {
            float4 a  = *(float4*)&As[cur][kk][ty * 4];
            float4 bb = *(float4*)&Bs[cur][kk][tx * 4];
            micro_fma2(acc2, a, bb);
        }
        if (kt < 31) {
            int nxt = cur ^ 1;
            As[nxt][kq * 4 + 0][jj] = aReg.x;
            As[nxt][kq * 4 + 1][jj] = aReg.y;
            As[nxt][kq * 4 + 2][jj] = aReg.z;
            As[nxt][kq * 4 + 3][jj] = aReg.w;
            *(float4*)&Bs[nxt][kb][hq * 4] = bReg;
            __syncthreads();
        }
    }

    float o[4][4];
#pragma unroll
    for (int rp = 0; rp < 2; rp++)
#pragma unroll
        for (int c = 0; c < 4; c++)
            upk2(acc2[rp][c], o[2 * rp][c], o[2 * rp + 1][c]);

#pragma unroll
    for (int r = 0; r < 4; r++) {
        float4 v = make_float4(o[r][0], o[r][1], o[r][2], o[r][3]);
        *(float4*)&c_out[((size_t)b * TD + j0 + ty * 4 + r) * H + h0 + tx * 4] = v;
    }
}

// ---------------------------------------------------------------------------
extern "C" void kernel_launch(void* const* d_in, const int* in_sizes, int n_in,
                              void* d_out, int out_size) {
    const float* enc = (const float*)d_in[0];  // [B,TE,H]
    const float* dec = (const float*)d_in[1];  // [B,TD,H]
    const float* W   = (const float*)d_in[2];  // [H,H]
    const float* U   = (const float*)d_in[3];  // [H,H]
    const float* V   = (const float*)d_in[4];  // [H,1]

    float* c_out = (float*)d_out;              // [B,TD,H]
    float* e_out = (float*)d_out + B * TD * H; // [B,TD,TE]

    zero_kernel<<<296, 256>>>();
    dim3 gg(24, 4, B);                         // K-split x2 -> 768 blocks
    gemm_fused<<<gg, 256>>>(enc, dec, W, U);
    energy_kernel<<<B * (TD / 4), 512>>>(V, e_out);
    dim3 gc(H / 64, TD / 64, B);
    ctx_gemm<<<gc, 256>>>(e_out, enc, c_out);
}